// round 2
// baseline (speedup 1.0000x reference)
#include <cuda_runtime.h>

// ---------------------------------------------------------------------------
// GraphAttentionWithMask: 4-head GAT, N=4096, F=512, D=64, E=128, M=64
//
// Pipeline:
//  K1 wh_kernel    : Wh[h][n][d] = sum_f (mask[n]*x[n][f]) * W[h][f][d]
//  K2 f12_kernel   : f1[h][n] = Wh[h][n]·a1[h],  f2 likewise
//  K3 adjp_kernel  : adjp[h][n][m] = sum_e adj[n][m][e]*aw[h][e]
//  K4 flash_kernel : per head, flash-attention style:
//                      S = adjp_rows @ adjp_colsᵀ  (mask = S>0)
//                      e = leaky(f1[i]+f2[j]); softmax over j of masked e
//                      head = elu(att @ Wh)
//  K5 final_kernel : out = leaky(cat(heads) @ Wd + bd)
// ---------------------------------------------------------------------------

#define N_  4096
#define F_  512
#define D_  64
#define H_  4
#define E_  128
#define M_  64
#define NEG_BIG (-9.0e15f)
#define SLOPE_ 0.2f

__device__ float g_Wh  [H_ * N_ * D_];
__device__ float g_adjp[H_ * N_ * M_];
__device__ float g_f1  [H_ * N_];
__device__ float g_f2  [H_ * N_];
__device__ float g_head[H_ * N_ * D_];

// ---------------------------------------------------------------------------
// K1: Wh = (mask*x) @ W[h].  Grid (N/64, H), 256 threads, 16x16 grid of 4x4.
// ---------------------------------------------------------------------------
__global__ void wh_kernel(const float* __restrict__ x,
                          const float* __restrict__ mask,
                          const float* __restrict__ W) {
    __shared__ float xT[64][68];   // [k][r]  (transposed, padded)
    __shared__ float Ws[64][64];   // [k][d]
    const int h  = blockIdx.y;
    const int n0 = blockIdx.x * 64;
    const int tid = threadIdx.x;
    const int ty = tid >> 4, tx = tid & 15;

    float acc[4][4] = {};

    for (int f0 = 0; f0 < F_; f0 += 64) {
        __syncthreads();
        // x tile (64 rows x 64 f), transposed into xT, mask applied
        for (int e = tid; e < 64 * 16; e += 256) {
            int r = e >> 4, k4 = (e & 15) * 4;
            float mk = mask[n0 + r];
            float4 xv = *(const float4*)&x[(size_t)(n0 + r) * F_ + f0 + k4];
            xT[k4 + 0][r] = xv.x * mk;
            xT[k4 + 1][r] = xv.y * mk;
            xT[k4 + 2][r] = xv.z * mk;
            xT[k4 + 3][r] = xv.w * mk;
        }
        // W tile direct
        for (int e = tid; e < 64 * 16; e += 256) {
            int rr = e >> 4, c4 = (e & 15) * 4;
            *(float4*)&Ws[rr][c4] =
                *(const float4*)&W[((size_t)h * F_ + f0 + rr) * D_ + c4];
        }
        __syncthreads();
        #pragma unroll 16
        for (int k = 0; k < 64; k++) {
            float4 a = *(float4*)&xT[k][4 * ty];
            float4 b = *(float4*)&Ws[k][4 * tx];
            acc[0][0] += a.x * b.x; acc[0][1] += a.x * b.y; acc[0][2] += a.x * b.z; acc[0][3] += a.x * b.w;
            acc[1][0] += a.y * b.x; acc[1][1] += a.y * b.y; acc[1][2] += a.y * b.z; acc[1][3] += a.y * b.w;
            acc[2][0] += a.z * b.x; acc[2][1] += a.z * b.y; acc[2][2] += a.z * b.z; acc[2][3] += a.z * b.w;
            acc[3][0] += a.w * b.x; acc[3][1] += a.w * b.y; acc[3][2] += a.w * b.z; acc[3][3] += a.w * b.w;
        }
    }
    #pragma unroll
    for (int i = 0; i < 4; i++)
        #pragma unroll
        for (int j = 0; j < 4; j++)
            g_Wh[((size_t)h * N_ + n0 + 4 * ty + i) * D_ + 4 * tx + j] = acc[i][j];
}

// ---------------------------------------------------------------------------
// K2: f1/f2 = Wh @ a1 / a2.  One warp per (h,n).
// ---------------------------------------------------------------------------
__global__ void f12_kernel(const float* __restrict__ a1,
                           const float* __restrict__ a2) {
    int w = (blockIdx.x * blockDim.x + threadIdx.x) >> 5;  // 0..H*N-1
    int lane = threadIdx.x & 31;
    int h = w / N_, n = w % N_;
    const float2 v  = ((const float2*)&g_Wh[((size_t)h * N_ + n) * D_])[lane];
    const float2 w1 = ((const float2*)&a1[h * D_])[lane];
    const float2 w2 = ((const float2*)&a2[h * D_])[lane];
    float s1 = v.x * w1.x + v.y * w1.y;
    float s2 = v.x * w2.x + v.y * w2.y;
    #pragma unroll
    for (int off = 16; off; off >>= 1) {
        s1 += __shfl_xor_sync(0xffffffffu, s1, off);
        s2 += __shfl_xor_sync(0xffffffffu, s2, off);
    }
    if (lane == 0) {
        g_f1[h * N_ + n] = s1;
        g_f2[h * N_ + n] = s2;
    }
}

// ---------------------------------------------------------------------------
// K3: adjp[h][n][m] = adj[n][m] · aw[h].  One warp per (n,m), all 4 heads.
// ---------------------------------------------------------------------------
__global__ void adjp_kernel(const float* __restrict__ adj,
                            const float* __restrict__ aw) {
    __shared__ float aws[H_ * E_];
    int tid = threadIdx.x;
    if (tid < H_ * E_) aws[tid] = aw[tid];
    if (tid + 256 < H_ * E_) aws[tid + 256] = aw[tid + 256];
    __syncthreads();

    int w = (blockIdx.x * blockDim.x + tid) >> 5;  // 0..N*M-1
    int lane = tid & 31;
    int n = w / M_, m = w % M_;
    float4 v = ((const float4*)&adj[(size_t)(n * M_ + m) * E_])[lane];
    float s[H_];
    #pragma unroll
    for (int h = 0; h < H_; h++) {
        const float4 aw4 = ((const float4*)&aws[h * E_])[lane];
        s[h] = v.x * aw4.x + v.y * aw4.y + v.z * aw4.z + v.w * aw4.w;
    }
    #pragma unroll
    for (int off = 16; off; off >>= 1) {
        #pragma unroll
        for (int h = 0; h < H_; h++)
            s[h] += __shfl_xor_sync(0xffffffffu, s[h], off);
    }
    if (lane == 0) {
        #pragma unroll
        for (int h = 0; h < H_; h++)
            g_adjp[((size_t)h * N_ + n) * M_ + m] = s[h];
    }
}

// ---------------------------------------------------------------------------
// K4: flash attention.  Grid (N/32, H), 256 threads.
// Thread (ty,tx) with ty=tid/16, tx=tid%16 owns rows {2ty,2ty+1},
// cols {4tx..4tx+3} of the 32x64 S tile, and dims {4tx..} of the 64-dim O.
// Dynamic smem layout (floats):
//   QaT[64][36], KaT[64][68], Vs[64][68], PT[64][36], f2s[64]
// ---------------------------------------------------------------------------
#define SM_QAT 0
#define SM_KAT (SM_QAT + 64 * 36)
#define SM_VS  (SM_KAT + 64 * 68)
#define SM_PT  (SM_VS  + 64 * 68)
#define SM_F2  (SM_PT  + 64 * 36)
#define SM_FLOATS (SM_F2 + 64)

__global__ void flash_kernel() {
    extern __shared__ float sm[];
    float* QaT = sm + SM_QAT;
    float* KaT = sm + SM_KAT;
    float* Vs  = sm + SM_VS;
    float* PT  = sm + SM_PT;
    float* f2s = sm + SM_F2;

    const int h  = blockIdx.y;
    const int i0 = blockIdx.x * 32;
    const int tid = threadIdx.x;
    const int ty = tid >> 4, tx = tid & 15;

    // Load Q tile (32 rows x 64 dims of adjp), transposed
    for (int e = tid; e < 32 * 16; e += 256) {
        int r = e >> 4, c4 = (e & 15) * 4;
        float4 q = *(const float4*)&g_adjp[((size_t)h * N_ + i0 + r) * M_ + c4];
        QaT[(c4 + 0) * 36 + r] = q.x;
        QaT[(c4 + 1) * 36 + r] = q.y;
        QaT[(c4 + 2) * 36 + r] = q.z;
        QaT[(c4 + 3) * 36 + r] = q.w;
    }
    float f1r[2];
    f1r[0] = g_f1[h * N_ + i0 + 2 * ty + 0];
    f1r[1] = g_f1[h * N_ + i0 + 2 * ty + 1];

    float m_[2] = {NEG_BIG, NEG_BIG};
    float l_[2] = {0.f, 0.f};
    float o[2][4] = {};
    __syncthreads();

    for (int jt = 0; jt < N_ / 64; jt++) {
        const int j0 = jt * 64;
        // Load K tile (transposed) + V tile (direct) + f2 slice
        for (int e = tid; e < 64 * 16; e += 256) {
            int c = e >> 4, d4 = (e & 15) * 4;
            float4 kv = *(const float4*)&g_adjp[((size_t)h * N_ + j0 + c) * M_ + d4];
            KaT[(d4 + 0) * 68 + c] = kv.x;
            KaT[(d4 + 1) * 68 + c] = kv.y;
            KaT[(d4 + 2) * 68 + c] = kv.z;
            KaT[(d4 + 3) * 68 + c] = kv.w;
            *(float4*)&Vs[c * 68 + d4] =
                *(const float4*)&g_Wh[((size_t)h * N_ + j0 + c) * D_ + d4];
        }
        if (tid < 64) f2s[tid] = g_f2[h * N_ + j0 + tid];
        __syncthreads();

        // S = Qa @ Kaᵀ (fp32)
        float s0[4] = {}, s1[4] = {};
        #pragma unroll 16
        for (int k = 0; k < 64; k++) {
            float2 q  = *(float2*)&QaT[k * 36 + 2 * ty];
            float4 kk = *(float4*)&KaT[k * 68 + 4 * tx];
            s0[0] += q.x * kk.x; s0[1] += q.x * kk.y; s0[2] += q.x * kk.z; s0[3] += q.x * kk.w;
            s1[0] += q.y * kk.x; s1[1] += q.y * kk.y; s1[2] += q.y * kk.z; s1[3] += q.y * kk.w;
        }

        // Scores + online softmax (per row i)
        float ev[4];
        #pragma unroll
        for (int j = 0; j < 4; j++) {
            ev[j] = f2s[4 * tx + j];
        }
        #pragma unroll
        for (int i = 0; i < 2; i++) {
            float* s = (i == 0) ? s0 : s1;
            float sc[4];
            float tmax = NEG_BIG;
            #pragma unroll
            for (int j = 0; j < 4; j++) {
                float e = f1r[i] + ev[j];
                e = (e > 0.f) ? e : SLOPE_ * e;       // leaky_relu
                sc[j] = e;
                float cand = (s[j] > 0.f) ? e : NEG_BIG;
                tmax = fmaxf(tmax, cand);
            }
            #pragma unroll
            for (int off = 8; off; off >>= 1)
                tmax = fmaxf(tmax, __shfl_xor_sync(0xffffffffu, tmax, off));

            float mnew = fmaxf(m_[i], tmax);
            float alpha = __expf(m_[i] - mnew);        // NEG_BIG-NEG_BIG=0 -> 1 (state is 0)
            float pj[4], psum = 0.f;
            #pragma unroll
            for (int j = 0; j < 4; j++) {
                float p = (s[j] > 0.f) ? __expf(sc[j] - mnew) : 0.f;
                pj[j] = p;
                psum += p;
            }
            #pragma unroll
            for (int off = 8; off; off >>= 1)
                psum += __shfl_xor_sync(0xffffffffu, psum, off);

            l_[i] = l_[i] * alpha + psum;
            m_[i] = mnew;
            #pragma unroll
            for (int j = 0; j < 4; j++) o[i][j] *= alpha;
            #pragma unroll
            for (int j = 0; j < 4; j++)
                PT[(4 * tx + j) * 36 + 2 * ty + i] = pj[j];
        }
        __syncthreads();

        // O += P @ V
        #pragma unroll 16
        for (int c = 0; c < 64; c++) {
            float2 p2 = *(float2*)&PT[c * 36 + 2 * ty];
            float4 v  = *(float4*)&Vs[c * 68 + 4 * tx];
            o[0][0] += p2.x * v.x; o[0][1] += p2.x * v.y; o[0][2] += p2.x * v.z; o[0][3] += p2.x * v.w;
            o[1][0] += p2.y * v.x; o[1][1] += p2.y * v.y; o[1][2] += p2.y * v.z; o[1][3] += p2.y * v.w;
        }
        __syncthreads();
    }

    // Epilogue: normalize + elu, write head output
    #pragma unroll
    for (int i = 0; i < 2; i++) {
        float inv = 1.f / l_[i];
        #pragma unroll
        for (int j = 0; j < 4; j++) {
            float v = o[i][j] * inv;
            v = (v > 0.f) ? v : (__expf(v) - 1.f);     // elu
            g_head[((size_t)h * N_ + i0 + 2 * ty + i) * D_ + 4 * tx + j] = v;
        }
    }
}

// ---------------------------------------------------------------------------
// K5: out = leaky( cat(heads) @ Wd + bd ).  Grid N/64, 256 threads.
// cat[n][h*64+dd] = g_head[h][n][dd]
// ---------------------------------------------------------------------------
__global__ void final_kernel(const float* __restrict__ Wd,
                             const float* __restrict__ bd,
                             float* __restrict__ out) {
    __shared__ float AT[64][68];   // [k][r]
    __shared__ float Ws[64][64];   // [k][d]
    const int n0 = blockIdx.x * 64;
    const int tid = threadIdx.x;
    const int ty = tid >> 4, tx = tid & 15;

    float acc[4][4] = {};

    for (int h = 0; h < H_; h++) {
        __syncthreads();
        for (int e = tid; e < 64 * 16; e += 256) {
            int r = e >> 4, k4 = (e & 15) * 4;
            float4 a = *(const float4*)&g_head[((size_t)h * N_ + n0 + r) * D_ + k4];
            AT[k4 + 0][r] = a.x;
            AT[k4 + 1][r] = a.y;
            AT[k4 + 2][r] = a.z;
            AT[k4 + 3][r] = a.w;
        }
        for (int e = tid; e < 64 * 16; e += 256) {
            int rr = e >> 4, c4 = (e & 15) * 4;
            *(float4*)&Ws[rr][c4] = *(const float4*)&Wd[(size_t)(h * 64 + rr) * D_ + c4];
        }
        __syncthreads();
        #pragma unroll 16
        for (int k = 0; k < 64; k++) {
            float4 a = *(float4*)&AT[k][4 * ty];
            float4 b = *(float4*)&Ws[k][4 * tx];
            acc[0][0] += a.x * b.x; acc[0][1] += a.x * b.y; acc[0][2] += a.x * b.z; acc[0][3] += a.x * b.w;
            acc[1][0] += a.y * b.x; acc[1][1] += a.y * b.y; acc[1][2] += a.y * b.z; acc[1][3] += a.y * b.w;
            acc[2][0] += a.z * b.x; acc[2][1] += a.z * b.y; acc[2][2] += a.z * b.z; acc[2][3] += a.z * b.w;
            acc[3][0] += a.w * b.x; acc[3][1] += a.w * b.y; acc[3][2] += a.w * b.z; acc[3][3] += a.w * b.w;
        }
    }
    #pragma unroll
    for (int j = 0; j < 4; j++) {
        float b = bd[4 * tx + j];
        #pragma unroll
        for (int i = 0; i < 4; i++) {
            float v = acc[i][j] + b;
            v = (v > 0.f) ? v : SLOPE_ * v;
            out[(size_t)(n0 + 4 * ty + i) * D_ + 4 * tx + j] = v;
        }
    }
}

// ---------------------------------------------------------------------------
extern "C" void kernel_launch(void* const* d_in, const int* in_sizes, int n_in,
                              void* d_out, int out_size) {
    const float* x    = (const float*)d_in[0];
    const float* mask = (const float*)d_in[1];
    const float* adj  = (const float*)d_in[2];
    const float* W    = (const float*)d_in[3];
    const float* a1   = (const float*)d_in[4];
    const float* a2   = (const float*)d_in[5];
    const float* aw   = (const float*)d_in[6];
    const float* Wd   = (const float*)d_in[7];
    const float* bd   = (const float*)d_in[8];
    float* out        = (float*)d_out;

    // Unconditional (no static guard): host-side attribute set is
    // deterministic and graph-capture-safe.
    cudaFuncSetAttribute(flash_kernel,
                         cudaFuncAttributeMaxDynamicSharedMemorySize,
                         SM_FLOATS * (int)sizeof(float));

    wh_kernel<<<dim3(N_ / 64, H_), 256>>>(x, mask, W);
    f12_kernel<<<(H_ * N_) / 8, 256>>>(a1, a2);
    adjp_kernel<<<(N_ * M_) / 8, 256>>>(adj, aw);
    flash_kernel<<<dim3(N_ / 32, H_), 256, SM_FLOATS * (int)sizeof(float)>>>();
    final_kernel<<<N_ / 64, 256>>>(Wd, bd, out);
}

// round 3
// speedup vs baseline: 1.4327x; 1.4327x over previous
#include <cuda_runtime.h>

// ---------------------------------------------------------------------------
// GraphAttentionWithMask: 4-head GAT, N=4096, F=512, D=64, E=128, M=64
//
//  K1 wh_kernel    : Wh[h][n][d] = (mask*x) @ W[h]
//  K2 f12_kernel   : f1/f2[h][n] = Wh[h][n] · a1/a2[h]
//  K3 adjp_kernel  : adjpT[h][m][n] = adj[n][m] · aw[h]   (TRANSPOSED layout)
//  K4 flash_kernel : flash attention, 64x64 tiles, 4x4 reg tile, float4 frags
//  K5 final_kernel : out = leaky(cat(heads) @ Wd + bd)
// ---------------------------------------------------------------------------

#define N_  4096
#define F_  512
#define D_  64
#define H_  4
#define E_  128
#define M_  64
#define NEG_BIG (-9.0e15f)
#define SLOPE_ 0.2f
#define PAD_ 68

__device__ float g_Wh   [H_ * N_ * D_];
__device__ float g_adjpT[H_ * M_ * N_];   // [h][m][n]  (n contiguous)
__device__ float g_f1   [H_ * N_];
__device__ float g_f2   [H_ * N_];
__device__ float g_head [H_ * N_ * D_];

// ---------------------------------------------------------------------------
// K1: Wh = (mask*x) @ W[h].  Grid (N/64, H), 256 threads, 4x4 reg tile.
// ---------------------------------------------------------------------------
__global__ void wh_kernel(const float* __restrict__ x,
                          const float* __restrict__ mask,
                          const float* __restrict__ W) {
    __shared__ float xT[64][68];   // [k][r]
    __shared__ float Ws[64][64];   // [k][d]
    const int h  = blockIdx.y;
    const int n0 = blockIdx.x * 64;
    const int tid = threadIdx.x;
    const int ty = tid >> 4, tx = tid & 15;

    float acc[4][4] = {};

    for (int f0 = 0; f0 < F_; f0 += 64) {
        __syncthreads();
        for (int e = tid; e < 64 * 16; e += 256) {
            int r = e >> 4, k4 = (e & 15) * 4;
            float mk = mask[n0 + r];
            float4 xv = *(const float4*)&x[(size_t)(n0 + r) * F_ + f0 + k4];
            xT[k4 + 0][r] = xv.x * mk;
            xT[k4 + 1][r] = xv.y * mk;
            xT[k4 + 2][r] = xv.z * mk;
            xT[k4 + 3][r] = xv.w * mk;
        }
        for (int e = tid; e < 64 * 16; e += 256) {
            int rr = e >> 4, c4 = (e & 15) * 4;
            *(float4*)&Ws[rr][c4] =
                *(const float4*)&W[((size_t)h * F_ + f0 + rr) * D_ + c4];
        }
        __syncthreads();
        #pragma unroll 8
        for (int k = 0; k < 64; k++) {
            float4 a = *(float4*)&xT[k][4 * ty];
            float4 b = *(float4*)&Ws[k][4 * tx];
            acc[0][0] += a.x * b.x; acc[0][1] += a.x * b.y; acc[0][2] += a.x * b.z; acc[0][3] += a.x * b.w;
            acc[1][0] += a.y * b.x; acc[1][1] += a.y * b.y; acc[1][2] += a.y * b.z; acc[1][3] += a.y * b.w;
            acc[2][0] += a.z * b.x; acc[2][1] += a.z * b.y; acc[2][2] += a.z * b.z; acc[2][3] += a.z * b.w;
            acc[3][0] += a.w * b.x; acc[3][1] += a.w * b.y; acc[3][2] += a.w * b.z; acc[3][3] += a.w * b.w;
        }
    }
    #pragma unroll
    for (int i = 0; i < 4; i++)
        #pragma unroll
        for (int j = 0; j < 4; j++)
            g_Wh[((size_t)h * N_ + n0 + 4 * ty + i) * D_ + 4 * tx + j] = acc[i][j];
}

// ---------------------------------------------------------------------------
// K2: f1/f2 = Wh @ a1/a2.  One warp per (h,n).
// ---------------------------------------------------------------------------
__global__ void f12_kernel(const float* __restrict__ a1,
                           const float* __restrict__ a2) {
    int w = (blockIdx.x * blockDim.x + threadIdx.x) >> 5;
    int lane = threadIdx.x & 31;
    int h = w / N_, n = w % N_;
    const float2 v  = ((const float2*)&g_Wh[((size_t)h * N_ + n) * D_])[lane];
    const float2 w1 = ((const float2*)&a1[h * D_])[lane];
    const float2 w2 = ((const float2*)&a2[h * D_])[lane];
    float s1 = v.x * w1.x + v.y * w1.y;
    float s2 = v.x * w2.x + v.y * w2.y;
    #pragma unroll
    for (int off = 16; off; off >>= 1) {
        s1 += __shfl_xor_sync(0xffffffffu, s1, off);
        s2 += __shfl_xor_sync(0xffffffffu, s2, off);
    }
    if (lane == 0) {
        g_f1[h * N_ + n] = s1;
        g_f2[h * N_ + n] = s2;
    }
}

// ---------------------------------------------------------------------------
// K3: adjpT[h][m][n] = adj[n][m] · aw[h].  One warp per (m,n); w = m*N + n
//     so consecutive warps write consecutive n (coalesced output).
// ---------------------------------------------------------------------------
__global__ void adjp_kernel(const float* __restrict__ adj,
                            const float* __restrict__ aw) {
    __shared__ float aws[H_ * E_];
    int tid = threadIdx.x;
    if (tid < H_ * E_) aws[tid] = aw[tid];
    if (tid + 256 < H_ * E_) aws[tid + 256] = aw[tid + 256];
    __syncthreads();

    int w = (blockIdx.x * blockDim.x + tid) >> 5;   // 0..M*N-1
    int lane = tid & 31;
    int m = w / N_, n = w % N_;
    float4 v = ((const float4*)&adj[(size_t)(n * M_ + m) * E_])[lane];
    float s[H_];
    #pragma unroll
    for (int h = 0; h < H_; h++) {
        const float4 aw4 = ((const float4*)&aws[h * E_])[lane];
        s[h] = v.x * aw4.x + v.y * aw4.y + v.z * aw4.z + v.w * aw4.w;
    }
    #pragma unroll
    for (int off = 16; off; off >>= 1) {
        #pragma unroll
        for (int h = 0; h < H_; h++)
            s[h] += __shfl_xor_sync(0xffffffffu, s[h], off);
    }
    if (lane == 0) {
        #pragma unroll
        for (int h = 0; h < H_; h++)
            g_adjpT[((size_t)h * M_ + m) * N_ + n] = s[h];
    }
}

// ---------------------------------------------------------------------------
// K4: flash attention.  Grid (N/64, H), 256 threads.  i-tile 64, j-tile 64.
// Thread (ty=tid/16, tx=tid%16) owns S rows 4ty..4ty+3, cols 4tx..4tx+3,
// and O rows 4ty..4ty+3, dims 4tx..4tx+3.  Both gemm fragments are float4.
// smem (floats): QT[64][PAD], KT[64][PAD], Vs[64][PAD], PT[64][PAD], f2s[64]
//   QT/KT: [k][i or j]   (direct rows of g_adjpT)
//   Vs   : [c][d]        (direct rows of g_Wh)
//   PT   : [c][i]        (written by softmax, float4 over i)
// ---------------------------------------------------------------------------
#define SM_QT 0
#define SM_KT (SM_QT + 64 * PAD_)
#define SM_VS (SM_KT + 64 * PAD_)
#define SM_PT (SM_VS + 64 * PAD_)
#define SM_F2 (SM_PT + 64 * PAD_)
#define SM_FLOATS (SM_F2 + 64)

__global__ void flash_kernel() {
    extern __shared__ float sm[];
    float* QT  = sm + SM_QT;
    float* KT  = sm + SM_KT;
    float* Vs  = sm + SM_VS;
    float* PT  = sm + SM_PT;
    float* f2s = sm + SM_F2;

    const int h  = blockIdx.y;
    const int i0 = blockIdx.x * 64;
    const int tid = threadIdx.x;
    const int ty = tid >> 4, tx = tid & 15;
    const size_t adjp_base = (size_t)h * M_ * N_;

    // Q tile: QT[k][i] = adjpT[h][k][i0+i]  (no transpose needed)
    for (int e = tid; e < 64 * 16; e += 256) {
        int k = e >> 4, i4 = (e & 15) * 4;
        *(float4*)&QT[k * PAD_ + i4] =
            *(const float4*)&g_adjpT[adjp_base + (size_t)k * N_ + i0 + i4];
    }
    float f1r[4];
    #pragma unroll
    for (int i = 0; i < 4; i++) f1r[i] = g_f1[h * N_ + i0 + 4 * ty + i];

    float m_[4], l_[4] = {0.f, 0.f, 0.f, 0.f};
    #pragma unroll
    for (int i = 0; i < 4; i++) m_[i] = NEG_BIG;
    float o[4][4] = {};

    for (int jt = 0; jt < N_ / 64; jt++) {
        const int j0 = jt * 64;
        __syncthreads();   // protect KT/Vs/PT from previous iteration readers
        for (int e = tid; e < 64 * 16; e += 256) {
            int k = e >> 4, j4 = (e & 15) * 4;
            *(float4*)&KT[k * PAD_ + j4] =
                *(const float4*)&g_adjpT[adjp_base + (size_t)k * N_ + j0 + j4];
            *(float4*)&Vs[k * PAD_ + j4] =
                *(const float4*)&g_Wh[((size_t)h * N_ + j0 + k) * D_ + j4];
        }
        if (tid < 64) f2s[tid] = g_f2[h * N_ + j0 + tid];
        __syncthreads();

        // S = Q @ Kᵀ  (4x4 per thread, float4 fragments)
        float s[4][4] = {};
        #pragma unroll 8
        for (int k = 0; k < 64; k++) {
            float4 a = *(float4*)&QT[k * PAD_ + 4 * ty];
            float4 b = *(float4*)&KT[k * PAD_ + 4 * tx];
            s[0][0] += a.x * b.x; s[0][1] += a.x * b.y; s[0][2] += a.x * b.z; s[0][3] += a.x * b.w;
            s[1][0] += a.y * b.x; s[1][1] += a.y * b.y; s[1][2] += a.y * b.z; s[1][3] += a.y * b.w;
            s[2][0] += a.z * b.x; s[2][1] += a.z * b.y; s[2][2] += a.z * b.z; s[2][3] += a.z * b.w;
            s[3][0] += a.w * b.x; s[3][1] += a.w * b.y; s[3][2] += a.w * b.z; s[3][3] += a.w * b.w;
        }

        // Softmax per row (16-lane butterfly across tx); p overwrites s.
        float f2v[4];
        #pragma unroll
        for (int j = 0; j < 4; j++) f2v[j] = f2s[4 * tx + j];

        #pragma unroll
        for (int i = 0; i < 4; i++) {
            float sc[4];
            float tmax = NEG_BIG;
            #pragma unroll
            for (int j = 0; j < 4; j++) {
                float e = f1r[i] + f2v[j];
                e = (e > 0.f) ? e : SLOPE_ * e;          // leaky_relu
                sc[j] = e;
                tmax = fmaxf(tmax, (s[i][j] > 0.f) ? e : NEG_BIG);
            }
            #pragma unroll
            for (int off = 8; off; off >>= 1)
                tmax = fmaxf(tmax, __shfl_xor_sync(0xffffffffu, tmax, off));

            float mnew = fmaxf(m_[i], tmax);
            float alpha = __expf(m_[i] - mnew);
            float psum = 0.f;
            #pragma unroll
            for (int j = 0; j < 4; j++) {
                float p = (s[i][j] > 0.f) ? __expf(sc[j] - mnew) : 0.f;
                s[i][j] = p;
                psum += p;
            }
            #pragma unroll
            for (int off = 8; off; off >>= 1)
                psum += __shfl_xor_sync(0xffffffffu, psum, off);

            l_[i] = l_[i] * alpha + psum;
            m_[i] = mnew;
            #pragma unroll
            for (int j = 0; j < 4; j++) o[i][j] *= alpha;
        }
        __syncthreads();   // PT readers from previous PV done (covered by top sync)

        // Write P transposed: PT[c][i], float4 over i.
        #pragma unroll
        for (int j = 0; j < 4; j++) {
            float4 pv = make_float4(s[0][j], s[1][j], s[2][j], s[3][j]);
            *(float4*)&PT[(4 * tx + j) * PAD_ + 4 * ty] = pv;
        }
        __syncthreads();

        // O += P @ V  (4x4 per thread, float4 fragments)
        #pragma unroll 8
        for (int c = 0; c < 64; c++) {
            float4 a = *(float4*)&PT[c * PAD_ + 4 * ty];
            float4 b = *(float4*)&Vs[c * PAD_ + 4 * tx];
            o[0][0] += a.x * b.x; o[0][1] += a.x * b.y; o[0][2] += a.x * b.z; o[0][3] += a.x * b.w;
            o[1][0] += a.y * b.x; o[1][1] += a.y * b.y; o[1][2] += a.y * b.z; o[1][3] += a.y * b.w;
            o[2][0] += a.z * b.x; o[2][1] += a.z * b.y; o[2][2] += a.z * b.z; o[2][3] += a.z * b.w;
            o[3][0] += a.w * b.x; o[3][1] += a.w * b.y; o[3][2] += a.w * b.z; o[3][3] += a.w * b.w;
        }
    }

    // Epilogue: normalize + elu
    #pragma unroll
    for (int i = 0; i < 4; i++) {
        float inv = 1.f / l_[i];
        #pragma unroll
        for (int j = 0; j < 4; j++) {
            float v = o[i][j] * inv;
            v = (v > 0.f) ? v : (__expf(v) - 1.f);
            g_head[((size_t)h * N_ + i0 + 4 * ty + i) * D_ + 4 * tx + j] = v;
        }
    }
}

// ---------------------------------------------------------------------------
// K5: out = leaky( cat(heads) @ Wd + bd ).  Grid N/64, 256 threads.
// ---------------------------------------------------------------------------
__global__ void final_kernel(const float* __restrict__ Wd,
                             const float* __restrict__ bd,
                             float* __restrict__ out) {
    __shared__ float AT[64][68];
    __shared__ float Ws[64][64];
    const int n0 = blockIdx.x * 64;
    const int tid = threadIdx.x;
    const int ty = tid >> 4, tx = tid & 15;

    float acc[4][4] = {};

    for (int h = 0; h < H_; h++) {
        __syncthreads();
        for (int e = tid; e < 64 * 16; e += 256) {
            int r = e >> 4, k4 = (e & 15) * 4;
            float4 a = *(const float4*)&g_head[((size_t)h * N_ + n0 + r) * D_ + k4];
            AT[k4 + 0][r] = a.x;
            AT[k4 + 1][r] = a.y;
            AT[k4 + 2][r] = a.z;
            AT[k4 + 3][r] = a.w;
        }
        for (int e = tid; e < 64 * 16; e += 256) {
            int rr = e >> 4, c4 = (e & 15) * 4;
            *(float4*)&Ws[rr][c4] = *(const float4*)&Wd[(size_t)(h * 64 + rr) * D_ + c4];
        }
        __syncthreads();
        #pragma unroll 8
        for (int k = 0; k < 64; k++) {
            float4 a = *(float4*)&AT[k][4 * ty];
            float4 b = *(float4*)&Ws[k][4 * tx];
            acc[0][0] += a.x * b.x; acc[0][1] += a.x * b.y; acc[0][2] += a.x * b.z; acc[0][3] += a.x * b.w;
            acc[1][0] += a.y * b.x; acc[1][1] += a.y * b.y; acc[1][2] += a.y * b.z; acc[1][3] += a.y * b.w;
            acc[2][0] += a.z * b.x; acc[2][1] += a.z * b.y; acc[2][2] += a.z * b.z; acc[2][3] += a.z * b.w;
            acc[3][0] += a.w * b.x; acc[3][1] += a.w * b.y; acc[3][2] += a.w * b.z; acc[3][3] += a.w * b.w;
        }
    }
    #pragma unroll
    for (int j = 0; j < 4; j++) {
        float b = bd[4 * tx + j];
        #pragma unroll
        for (int i = 0; i < 4; i++) {
            float v = acc[i][j] + b;
            v = (v > 0.f) ? v : SLOPE_ * v;
            out[(size_t)(n0 + 4 * ty + i) * D_ + 4 * tx + j] = v;
        }
    }
}

// ---------------------------------------------------------------------------
extern "C" void kernel_launch(void* const* d_in, const int* in_sizes, int n_in,
                              void* d_out, int out_size) {
    const float* x    = (const float*)d_in[0];
    const float* mask = (const float*)d_in[1];
    const float* adj  = (const float*)d_in[2];
    const float* W    = (const float*)d_in[3];
    const float* a1   = (const float*)d_in[4];
    const float* a2   = (const float*)d_in[5];
    const float* aw   = (const float*)d_in[6];
    const float* Wd   = (const float*)d_in[7];
    const float* bd   = (const float*)d_in[8];
    float* out        = (float*)d_out;

    cudaFuncSetAttribute(flash_kernel,
                         cudaFuncAttributeMaxDynamicSharedMemorySize,
                         SM_FLOATS * (int)sizeof(float));

    wh_kernel<<<dim3(N_ / 64, H_), 256>>>(x, mask, W);
    f12_kernel<<<(H_ * N_) / 8, 256>>>(a1, a2);
    adjp_kernel<<<(N_ * M_) / 8, 256>>>(adj, aw);
    flash_kernel<<<dim3(N_ / 64, H_), 256, SM_FLOATS * (int)sizeof(float)>>>();
    final_kernel<<<N_ / 64, 256>>>(Wd, bd, out);
}

// round 4
// speedup vs baseline: 1.4826x; 1.0348x over previous
#include <cuda_runtime.h>

// ---------------------------------------------------------------------------
// GraphAttentionWithMask: 4-head GAT, N=4096, F=512, D=64, E=128, M=64
//
//  K1 wh_kernel    : Wh[h][n][d] = (mask*x) @ W[h]   (also writes WhT[h][d][n])
//  K2 f12_kernel   : f1/f2[h][n] = Wh[h][n] · a1/a2[h]
//  K3 adjp_kernel  : adjp[h][n][m] = adj[n][m] · aw[h]
//  K4 flash_kernel : flash attention, 64x64 tiles, packed-k FFMA2 (f32x2),
//                    split-KV x2 (grid z), partials to scratch
//  K4b merge_kernel: combine the two KV splits, apply elu
//  K5 final_kernel : out = leaky(cat(heads) @ Wd + bd)
// ---------------------------------------------------------------------------

#define N_  4096
#define F_  512
#define D_  64
#define H_  4
#define E_  128
#define M_  64
#define HN_ (H_ * N_)
#define NEG_BIG (-9.0e15f)
#define SLOPE_ 0.2f

typedef unsigned long long u64t;

// packed fp32x2 FMA: acc.lo += a.lo*b.lo ; acc.hi += a.hi*b.hi
#define FMA2(acc, a, b) \
    asm("fma.rn.f32x2 %0, %1, %2, %0;" : "+l"(acc) : "l"(a), "l"(b))

__device__ __forceinline__ float unpack_add(u64t v) {
    float lo, hi;
    asm("mov.b64 {%0, %1}, %2;" : "=f"(lo), "=f"(hi) : "l"(v));
    return lo + hi;
}

__device__ float g_Wh  [H_ * N_ * D_];
__device__ float g_WhT [H_ * D_ * N_];   // [h][d][n]  (n contiguous)
__device__ float g_adjp[H_ * N_ * M_];   // [h][n][m]  (m contiguous)
__device__ float g_f1  [H_ * N_];
__device__ float g_f2  [H_ * N_];
__device__ float g_head[H_ * N_ * D_];
// split-KV partials: [split][h][n]
__device__ float g_po[2 * H_ * N_ * D_];
__device__ float g_pm[2 * H_ * N_];
__device__ float g_pl[2 * H_ * N_];

// ---------------------------------------------------------------------------
// K1: Wh = (mask*x) @ W[h].  Grid (N/64, H), 256 threads, 4x4 reg tile.
// ---------------------------------------------------------------------------
__global__ void wh_kernel(const float* __restrict__ x,
                          const float* __restrict__ mask,
                          const float* __restrict__ W) {
    __shared__ float xT[64][68];   // [k][r]
    __shared__ float Ws[64][64];   // [k][d]
    const int h  = blockIdx.y;
    const int n0 = blockIdx.x * 64;
    const int tid = threadIdx.x;
    const int ty = tid >> 4, tx = tid & 15;

    float acc[4][4] = {};

    for (int f0 = 0; f0 < F_; f0 += 64) {
        __syncthreads();
        for (int e = tid; e < 64 * 16; e += 256) {
            int r = e >> 4, k4 = (e & 15) * 4;
            float mk = mask[n0 + r];
            float4 xv = *(const float4*)&x[(size_t)(n0 + r) * F_ + f0 + k4];
            xT[k4 + 0][r] = xv.x * mk;
            xT[k4 + 1][r] = xv.y * mk;
            xT[k4 + 2][r] = xv.z * mk;
            xT[k4 + 3][r] = xv.w * mk;
        }
        for (int e = tid; e < 64 * 16; e += 256) {
            int rr = e >> 4, c4 = (e & 15) * 4;
            *(float4*)&Ws[rr][c4] =
                *(const float4*)&W[((size_t)h * F_ + f0 + rr) * D_ + c4];
        }
        __syncthreads();
        #pragma unroll 8
        for (int k = 0; k < 64; k++) {
            float4 a = *(float4*)&xT[k][4 * ty];
            float4 b = *(float4*)&Ws[k][4 * tx];
            acc[0][0] += a.x * b.x; acc[0][1] += a.x * b.y; acc[0][2] += a.x * b.z; acc[0][3] += a.x * b.w;
            acc[1][0] += a.y * b.x; acc[1][1] += a.y * b.y; acc[1][2] += a.y * b.z; acc[1][3] += a.y * b.w;
            acc[2][0] += a.z * b.x; acc[2][1] += a.z * b.y; acc[2][2] += a.z * b.z; acc[2][3] += a.z * b.w;
            acc[3][0] += a.w * b.x; acc[3][1] += a.w * b.y; acc[3][2] += a.w * b.z; acc[3][3] += a.w * b.w;
        }
    }
    #pragma unroll
    for (int i = 0; i < 4; i++)
        #pragma unroll
        for (int j = 0; j < 4; j++)
            g_Wh[((size_t)h * N_ + n0 + 4 * ty + i) * D_ + 4 * tx + j] = acc[i][j];
    // transposed copy for flash PV gemm (float4 over n)
    #pragma unroll
    for (int j = 0; j < 4; j++) {
        float4 col = make_float4(acc[0][j], acc[1][j], acc[2][j], acc[3][j]);
        *(float4*)&g_WhT[((size_t)h * D_ + 4 * tx + j) * N_ + n0 + 4 * ty] = col;
    }
}

// ---------------------------------------------------------------------------
// K2: f1/f2 = Wh @ a1/a2.  One warp per (h,n).
// ---------------------------------------------------------------------------
__global__ void f12_kernel(const float* __restrict__ a1,
                           const float* __restrict__ a2) {
    int w = (blockIdx.x * blockDim.x + threadIdx.x) >> 5;
    int lane = threadIdx.x & 31;
    int h = w / N_, n = w % N_;
    const float2 v  = ((const float2*)&g_Wh[((size_t)h * N_ + n) * D_])[lane];
    const float2 w1 = ((const float2*)&a1[h * D_])[lane];
    const float2 w2 = ((const float2*)&a2[h * D_])[lane];
    float s1 = v.x * w1.x + v.y * w1.y;
    float s2 = v.x * w2.x + v.y * w2.y;
    #pragma unroll
    for (int off = 16; off; off >>= 1) {
        s1 += __shfl_xor_sync(0xffffffffu, s1, off);
        s2 += __shfl_xor_sync(0xffffffffu, s2, off);
    }
    if (lane == 0) {
        g_f1[h * N_ + n] = s1;
        g_f2[h * N_ + n] = s2;
    }
}

// ---------------------------------------------------------------------------
// K3: adjp[h][n][m] = adj[n][m] · aw[h].  One warp per (n,m), all 4 heads.
// ---------------------------------------------------------------------------
__global__ void adjp_kernel(const float* __restrict__ adj,
                            const float* __restrict__ aw) {
    __shared__ float aws[H_ * E_];
    int tid = threadIdx.x;
    if (tid < H_ * E_) aws[tid] = aw[tid];
    if (tid + 256 < H_ * E_) aws[tid + 256] = aw[tid + 256];
    __syncthreads();

    int w = (blockIdx.x * blockDim.x + tid) >> 5;   // 0..N*M-1
    int lane = tid & 31;
    int n = w / M_, m = w % M_;
    float4 v = ((const float4*)&adj[(size_t)(n * M_ + m) * E_])[lane];
    float s[H_];
    #pragma unroll
    for (int h = 0; h < H_; h++) {
        const float4 aw4 = ((const float4*)&aws[h * E_])[lane];
        s[h] = v.x * aw4.x + v.y * aw4.y + v.z * aw4.z + v.w * aw4.w;
    }
    #pragma unroll
    for (int off = 16; off; off >>= 1) {
        #pragma unroll
        for (int h = 0; h < H_; h++)
            s[h] += __shfl_xor_sync(0xffffffffu, s[h], off);
    }
    if (lane == 0) {
        #pragma unroll
        for (int h = 0; h < H_; h++)
            g_adjp[((size_t)h * N_ + n) * M_ + m] = s[h];
    }
}

// ---------------------------------------------------------------------------
// K4: flash attention, packed-k FFMA2, split-KV x2.
// Grid (N/64, H, 2), 256 threads.  Thread (ty=tid/16, tx=tid%16) owns
// S rows 4ty..4ty+3, cols 4tx..4tx+3 and O rows 4ty.., dims 4tx...
// All smem tiles are [row][k]-major (k contiguous) with a 16B-chunk XOR
// swizzle so that fragment reads (rows stride 4 in tx/ty) are conflict-free:
//   float index = row*68 + 4*((chunk) ^ ((row>>2)&7)),  chunk = k/4
//   QT[i][k]=adjp[i0+i][k]  KT[j][k]=adjp[j0+j][k]
//   VT[d][c]=WhT[d][j0+c]   P [i][j]
// ---------------------------------------------------------------------------
#define FP_ 68
#define SMIDX(row, chunk) ((row) * FP_ + 4 * ((chunk) ^ (((row) >> 2) & 7)))
#define SM_QT 0
#define SM_KT (SM_QT + 64 * FP_)
#define SM_VT (SM_KT + 64 * FP_)
#define SM_P  (SM_VT + 64 * FP_)
#define SM_F2 (SM_P  + 64 * FP_)
#define SM_FLOATS (SM_F2 + 64)

__global__ void __launch_bounds__(256, 2) flash_kernel() {
    extern __shared__ float sm[];
    float* QT  = sm + SM_QT;
    float* KT  = sm + SM_KT;
    float* VT  = sm + SM_VT;
    float* P   = sm + SM_P;
    float* f2s = sm + SM_F2;

    const int h  = blockIdx.y;
    const int i0 = blockIdx.x * 64;
    const int sp = blockIdx.z;            // KV split 0/1
    const int tid = threadIdx.x;
    const int ty = tid >> 4, tx = tid & 15;

    // Q tile
    for (int e = tid; e < 64 * 16; e += 256) {
        int r = e >> 4, c = e & 15;
        *(float4*)&QT[SMIDX(r, c)] =
            *(const float4*)&g_adjp[((size_t)h * N_ + i0 + r) * M_ + 4 * c];
    }
    float f1r[4];
    #pragma unroll
    for (int i = 0; i < 4; i++) f1r[i] = g_f1[h * N_ + i0 + 4 * ty + i];

    float m_[4], l_[4] = {0.f, 0.f, 0.f, 0.f};
    #pragma unroll
    for (int i = 0; i < 4; i++) m_[i] = NEG_BIG;
    float o[4][4] = {};

    for (int jt = sp * 32; jt < sp * 32 + 32; jt++) {
        const int j0 = jt * 64;
        __syncthreads();   // prev-iter PV (reads P, VT) done before overwrite
        for (int e = tid; e < 64 * 16; e += 256) {
            int r = e >> 4, c = e & 15;
            *(float4*)&KT[SMIDX(r, c)] =
                *(const float4*)&g_adjp[((size_t)h * N_ + j0 + r) * M_ + 4 * c];
            *(float4*)&VT[SMIDX(r, c)] =
                *(const float4*)&g_WhT[((size_t)h * D_ + r) * N_ + j0 + 4 * c];
        }
        if (tid < 64) f2s[tid] = g_f2[h * N_ + j0 + tid];
        __syncthreads();

        // ---- S = Q @ K^T, k packed in pairs (two lanes of f32x2) ----
        u64t s2[4][4] = {};
        #pragma unroll 4
        for (int kq = 0; kq < 16; kq++) {
            ulonglong2 A[4], B[4];
            #pragma unroll
            for (int i = 0; i < 4; i++)
                A[i] = *(const ulonglong2*)&QT[SMIDX(4 * ty + i, kq)];
            #pragma unroll
            for (int j = 0; j < 4; j++)
                B[j] = *(const ulonglong2*)&KT[SMIDX(4 * tx + j, kq)];
            #pragma unroll
            for (int i = 0; i < 4; i++)
                #pragma unroll
                for (int j = 0; j < 4; j++) {
                    FMA2(s2[i][j], A[i].x, B[j].x);
                    FMA2(s2[i][j], A[i].y, B[j].y);
                }
        }
        float s[4][4];
        #pragma unroll
        for (int i = 0; i < 4; i++)
            #pragma unroll
            for (int j = 0; j < 4; j++) s[i][j] = unpack_add(s2[i][j]);

        // ---- masked online softmax ----
        float f2v[4];
        #pragma unroll
        for (int j = 0; j < 4; j++) f2v[j] = f2s[4 * tx + j];

        #pragma unroll
        for (int i = 0; i < 4; i++) {
            float sc[4];
            float tmax = NEG_BIG;
            #pragma unroll
            for (int j = 0; j < 4; j++) {
                float e = f1r[i] + f2v[j];
                e = (e > 0.f) ? e : SLOPE_ * e;          // leaky_relu
                sc[j] = e;
                tmax = fmaxf(tmax, (s[i][j] > 0.f) ? e : NEG_BIG);
            }
            #pragma unroll
            for (int off = 8; off; off >>= 1)
                tmax = fmaxf(tmax, __shfl_xor_sync(0xffffffffu, tmax, off));

            float mnew = fmaxf(m_[i], tmax);
            float alpha = __expf(m_[i] - mnew);
            float psum = 0.f;
            #pragma unroll
            for (int j = 0; j < 4; j++) {
                float p = (s[i][j] > 0.f) ? __expf(sc[j] - mnew) : 0.f;
                s[i][j] = p;
                psum += p;
            }
            #pragma unroll
            for (int off = 8; off; off >>= 1)
                psum += __shfl_xor_sync(0xffffffffu, psum, off);

            l_[i] = l_[i] * alpha + psum;
            m_[i] = mnew;
            #pragma unroll
            for (int j = 0; j < 4; j++) o[i][j] *= alpha;
        }

        // write P[i][j] (row-major, swizzled, float4 over own cols)
        #pragma unroll
        for (int i = 0; i < 4; i++)
            *(float4*)&P[SMIDX(4 * ty + i, tx)] =
                make_float4(s[i][0], s[i][1], s[i][2], s[i][3]);
        __syncthreads();

        // ---- O += P @ V, c packed in pairs ----
        u64t o2[4][4] = {};
        #pragma unroll 4
        for (int cq = 0; cq < 16; cq++) {
            ulonglong2 A[4], B[4];
            #pragma unroll
            for (int i = 0; i < 4; i++)
                A[i] = *(const ulonglong2*)&P[SMIDX(4 * ty + i, cq)];
            #pragma unroll
            for (int j = 0; j < 4; j++)
                B[j] = *(const ulonglong2*)&VT[SMIDX(4 * tx + j, cq)];
            #pragma unroll
            for (int i = 0; i < 4; i++)
                #pragma unroll
                for (int j = 0; j < 4; j++) {
                    FMA2(o2[i][j], A[i].x, B[j].x);
                    FMA2(o2[i][j], A[i].y, B[j].y);
                }
        }
        #pragma unroll
        for (int i = 0; i < 4; i++)
            #pragma unroll
            for (int j = 0; j < 4; j++) o[i][j] += unpack_add(o2[i][j]);
    }

    // partial epilogue: unnormalized o at running max, plus (m, l)
    const int rowb = (sp * H_ + h) * N_ + i0;
    #pragma unroll
    for (int i = 0; i < 4; i++) {
        int rr = rowb + 4 * ty + i;
        if (tx == 0) { g_pm[rr] = m_[i]; g_pl[rr] = l_[i]; }
        *(float4*)&g_po[(size_t)rr * D_ + 4 * tx] =
            make_float4(o[i][0], o[i][1], o[i][2], o[i][3]);
    }
}

// ---------------------------------------------------------------------------
// K4b: merge the two KV splits, normalize, elu.  One thread per (h,n,d4).
// ---------------------------------------------------------------------------
__global__ void merge_kernel() {
    int idx = blockIdx.x * 256 + threadIdx.x;     // < H*N*16
    int d4 = (idx & 15) * 4;
    int hn = idx >> 4;
    float m1 = g_pm[hn],       l1 = g_pl[hn];
    float m2 = g_pm[HN_ + hn], l2 = g_pl[HN_ + hn];
    float m  = fmaxf(m1, m2);
    float w1 = __expf(m1 - m), w2 = __expf(m2 - m);
    float inv = 1.f / (l1 * w1 + l2 * w2);
    float4 o1 = *(const float4*)&g_po[(size_t)hn * D_ + d4];
    float4 o2 = *(const float4*)&g_po[(size_t)(HN_ + hn) * D_ + d4];
    float4 v;
    v.x = (o1.x * w1 + o2.x * w2) * inv;
    v.y = (o1.y * w1 + o2.y * w2) * inv;
    v.z = (o1.z * w1 + o2.z * w2) * inv;
    v.w = (o1.w * w1 + o2.w * w2) * inv;
    v.x = (v.x > 0.f) ? v.x : (__expf(v.x) - 1.f);
    v.y = (v.y > 0.f) ? v.y : (__expf(v.y) - 1.f);
    v.z = (v.z > 0.f) ? v.z : (__expf(v.z) - 1.f);
    v.w = (v.w > 0.f) ? v.w : (__expf(v.w) - 1.f);
    *(float4*)&g_head[(size_t)hn * D_ + d4] = v;
}

// ---------------------------------------------------------------------------
// K5: out = leaky( cat(heads) @ Wd + bd ).  Grid N/64, 256 threads.
// ---------------------------------------------------------------------------
__global__ void final_kernel(const float* __restrict__ Wd,
                             const float* __restrict__ bd,
                             float* __restrict__ out) {
    __shared__ float AT[64][68];
    __shared__ float Ws[64][64];
    const int n0 = blockIdx.x * 64;
    const int tid = threadIdx.x;
    const int ty = tid >> 4, tx = tid & 15;

    float acc[4][4] = {};

    for (int h = 0; h < H_; h++) {
        __syncthreads();
        for (int e = tid; e < 64 * 16; e += 256) {
            int r = e >> 4, k4 = (e & 15) * 4;
            float4 a = *(const float4*)&g_head[((size_t)h * N_ + n0 + r) * D_ + k4];
            AT[k4 + 0][r] = a.x;
            AT[k4 + 1][r] = a.y;
            AT[k4 + 2][r] = a.z;
            AT[k4 + 3][r] = a.w;
        }
        for (int e = tid; e < 64 * 16; e += 256) {
            int rr = e >> 4, c4 = (e & 15) * 4;
            *(float4*)&Ws[rr][c4] = *(const float4*)&Wd[(size_t)(h * 64 + rr) * D_ + c4];
        }
        __syncthreads();
        #pragma unroll 8
        for (int k = 0; k < 64; k++) {
            float4 a = *(float4*)&AT[k][4 * ty];
            float4 b = *(float4*)&Ws[k][4 * tx];
            acc[0][0] += a.x * b.x; acc[0][1] += a.x * b.y; acc[0][2] += a.x * b.z; acc[0][3] += a.x * b.w;
            acc[1][0] += a.y * b.x; acc[1][1] += a.y * b.y; acc[1][2] += a.y * b.z; acc[1][3] += a.y * b.w;
            acc[2][0] += a.z * b.x; acc[2][1] += a.z * b.y; acc[2][2] += a.z * b.z; acc[2][3] += a.z * b.w;
            acc[3][0] += a.w * b.x; acc[3][1] += a.w * b.y; acc[3][2] += a.w * b.z; acc[3][3] += a.w * b.w;
        }
    }
    #pragma unroll
    for (int j = 0; j < 4; j++) {
        float b = bd[4 * tx + j];
        #pragma unroll
        for (int i = 0; i < 4; i++) {
            float v = acc[i][j] + b;
            v = (v > 0.f) ? v : SLOPE_ * v;
            out[(size_t)(n0 + 4 * ty + i) * D_ + 4 * tx + j] = v;
        }
    }
}

// ---------------------------------------------------------------------------
extern "C" void kernel_launch(void* const* d_in, const int* in_sizes, int n_in,
                              void* d_out, int out_size) {
    const float* x    = (const float*)d_in[0];
    const float* mask = (const float*)d_in[1];
    const float* adj  = (const float*)d_in[2];
    const float* W    = (const float*)d_in[3];
    const float* a1   = (const float*)d_in[4];
    const float* a2   = (const float*)d_in[5];
    const float* aw   = (const float*)d_in[6];
    const float* Wd   = (const float*)d_in[7];
    const float* bd   = (const float*)d_in[8];
    float* out        = (float*)d_out;

    cudaFuncSetAttribute(flash_kernel,
                         cudaFuncAttributeMaxDynamicSharedMemorySize,
                         SM_FLOATS * (int)sizeof(float));

    wh_kernel<<<dim3(N_ / 64, H_), 256>>>(x, mask, W);
    f12_kernel<<<(H_ * N_) / 8, 256>>>(a1, a2);
    adjp_kernel<<<(N_ * M_) / 8, 256>>>(adj, aw);
    flash_kernel<<<dim3(N_ / 64, H_, 2), 256, SM_FLOATS * (int)sizeof(float)>>>();
    merge_kernel<<<(HN_ * 16) / 256, 256>>>();
    final_kernel<<<N_ / 64, 256>>>(Wd, bd, out);
}

// round 7
// speedup vs baseline: 1.6104x; 1.0862x over previous
#include <cuda_runtime.h>

// ---------------------------------------------------------------------------
// GraphAttentionWithMask: 4-head GAT, N=4096, F=512, D=64, E=128, M=64
//
//  K1 wh_kernel    : Wh[h][n][d] = (mask*x) @ W[h]   (also writes WhT[h][d][n])
//  K2 f12_kernel   : f1/f2[h][n]; also u=exp(f2), w=exp(0.2*f2)
//  K3 adjp_kernel  : adjp[h][n][m] = adj[n][m] · aw[h]
//  K4 flash_kernel : masked attention with factored softmax:
//                    p_ij = [S_ij>0] * ( f2_j > -f1_i ? u_j : r_i*w_j )
//                    (r_i = exp(-0.8 f1_i));  O_i = sum p v / sum p
//                    -> no exp/max/rescale in the loop.  FFMA2 gemms,
//                    fully unrolled (compile-time swizzle), split-KV x2.
//  K4b merge_kernel: (o1+o2)/(l1+l2), elu
//  K5 final_kernel : out = leaky(cat(heads) @ Wd + bd)
// ---------------------------------------------------------------------------

#define N_  4096
#define F_  512
#define D_  64
#define H_  4
#define E_  128
#define M_  64
#define HN_ (H_ * N_)
#define SLOPE_ 0.2f

typedef unsigned long long u64t;

// packed fp32x2 FMA: acc.lo += a.lo*b.lo ; acc.hi += a.hi*b.hi
#define FMA2(acc, a, b) \
    asm("fma.rn.f32x2 %0, %1, %2, %0;" : "+l"(acc) : "l"(a), "l"(b))

__device__ __forceinline__ float unpack_add(u64t v) {
    float lo, hi;
    asm("mov.b64 {%0, %1}, %2;" : "=f"(lo), "=f"(hi) : "l"(v));
    return lo + hi;
}

__device__ float g_Wh  [H_ * N_ * D_];
__device__ float g_WhT [H_ * D_ * N_];   // [h][d][n]  (n contiguous)
__device__ float g_adjp[H_ * N_ * M_];   // [h][n][m]  (m contiguous)
__device__ float g_f1  [H_ * N_];
__device__ float g_f2  [H_ * N_];
__device__ float g_u   [H_ * N_];        // exp(f2)
__device__ float g_w   [H_ * N_];        // exp(0.2 f2)
__device__ float g_head[H_ * N_ * D_];
// split-KV partials: [split][h][n]
__device__ float g_po[2 * H_ * N_ * D_];
__device__ float g_pl[2 * H_ * N_];

// ---------------------------------------------------------------------------
// K1: Wh = (mask*x) @ W[h].  Grid (N/64, H), 256 threads, 4x4 reg tile.
// ---------------------------------------------------------------------------
__global__ void wh_kernel(const float* __restrict__ x,
                          const float* __restrict__ mask,
                          const float* __restrict__ W) {
    __shared__ float xT[64][68];   // [k][r]
    __shared__ float Ws[64][64];   // [k][d]
    const int h  = blockIdx.y;
    const int n0 = blockIdx.x * 64;
    const int tid = threadIdx.x;
    const int ty = tid >> 4, tx = tid & 15;

    float acc[4][4] = {};

    for (int f0 = 0; f0 < F_; f0 += 64) {
        __syncthreads();
        for (int e = tid; e < 64 * 16; e += 256) {
            int r = e >> 4, k4 = (e & 15) * 4;
            float mk = mask[n0 + r];
            float4 xv = *(const float4*)&x[(size_t)(n0 + r) * F_ + f0 + k4];
            xT[k4 + 0][r] = xv.x * mk;
            xT[k4 + 1][r] = xv.y * mk;
            xT[k4 + 2][r] = xv.z * mk;
            xT[k4 + 3][r] = xv.w * mk;
        }
        for (int e = tid; e < 64 * 16; e += 256) {
            int rr = e >> 4, c4 = (e & 15) * 4;
            *(float4*)&Ws[rr][c4] =
                *(const float4*)&W[((size_t)h * F_ + f0 + rr) * D_ + c4];
        }
        __syncthreads();
        #pragma unroll 8
        for (int k = 0; k < 64; k++) {
            float4 a = *(float4*)&xT[k][4 * ty];
            float4 b = *(float4*)&Ws[k][4 * tx];
            acc[0][0] += a.x * b.x; acc[0][1] += a.x * b.y; acc[0][2] += a.x * b.z; acc[0][3] += a.x * b.w;
            acc[1][0] += a.y * b.x; acc[1][1] += a.y * b.y; acc[1][2] += a.y * b.z; acc[1][3] += a.y * b.w;
            acc[2][0] += a.z * b.x; acc[2][1] += a.z * b.y; acc[2][2] += a.z * b.z; acc[2][3] += a.z * b.w;
            acc[3][0] += a.w * b.x; acc[3][1] += a.w * b.y; acc[3][2] += a.w * b.z; acc[3][3] += a.w * b.w;
        }
    }
    #pragma unroll
    for (int i = 0; i < 4; i++)
        #pragma unroll
        for (int j = 0; j < 4; j++)
            g_Wh[((size_t)h * N_ + n0 + 4 * ty + i) * D_ + 4 * tx + j] = acc[i][j];
    #pragma unroll
    for (int j = 0; j < 4; j++) {
        float4 col = make_float4(acc[0][j], acc[1][j], acc[2][j], acc[3][j]);
        *(float4*)&g_WhT[((size_t)h * D_ + 4 * tx + j) * N_ + n0 + 4 * ty] = col;
    }
}

// ---------------------------------------------------------------------------
// K2: f1/f2 = Wh @ a1/a2; u = exp(f2), w = exp(0.2 f2).  One warp per (h,n).
// ---------------------------------------------------------------------------
__global__ void f12_kernel(const float* __restrict__ a1,
                           const float* __restrict__ a2) {
    int w = (blockIdx.x * blockDim.x + threadIdx.x) >> 5;
    int lane = threadIdx.x & 31;
    int h = w / N_, n = w % N_;
    const float2 v  = ((const float2*)&g_Wh[((size_t)h * N_ + n) * D_])[lane];
    const float2 w1 = ((const float2*)&a1[h * D_])[lane];
    const float2 w2 = ((const float2*)&a2[h * D_])[lane];
    float s1 = v.x * w1.x + v.y * w1.y;
    float s2 = v.x * w2.x + v.y * w2.y;
    #pragma unroll
    for (int off = 16; off; off >>= 1) {
        s1 += __shfl_xor_sync(0xffffffffu, s1, off);
        s2 += __shfl_xor_sync(0xffffffffu, s2, off);
    }
    if (lane == 0) {
        g_f1[h * N_ + n] = s1;
        g_f2[h * N_ + n] = s2;
        g_u [h * N_ + n] = __expf(s2);
        g_w [h * N_ + n] = __expf(0.2f * s2);
    }
}

// ---------------------------------------------------------------------------
// K3: adjp[h][n][m] = adj[n][m] · aw[h].  One warp per (n,m), all 4 heads.
// ---------------------------------------------------------------------------
__global__ void adjp_kernel(const float* __restrict__ adj,
                            const float* __restrict__ aw) {
    __shared__ float aws[H_ * E_];
    int tid = threadIdx.x;
    if (tid < H_ * E_) aws[tid] = aw[tid];
    if (tid + 256 < H_ * E_) aws[tid + 256] = aw[tid + 256];
    __syncthreads();

    int w = (blockIdx.x * blockDim.x + tid) >> 5;   // 0..N*M-1
    int lane = tid & 31;
    int n = w / M_, m = w % M_;
    float4 v = ((const float4*)&adj[(size_t)(n * M_ + m) * E_])[lane];
    float s[H_];
    #pragma unroll
    for (int h = 0; h < H_; h++) {
        const float4 aw4 = ((const float4*)&aws[h * E_])[lane];
        s[h] = v.x * aw4.x + v.y * aw4.y + v.z * aw4.z + v.w * aw4.w;
    }
    #pragma unroll
    for (int off = 16; off; off >>= 1) {
        #pragma unroll
        for (int h = 0; h < H_; h++)
            s[h] += __shfl_xor_sync(0xffffffffu, s[h], off);
    }
    if (lane == 0) {
        #pragma unroll
        for (int h = 0; h < H_; h++)
            g_adjp[((size_t)h * N_ + n) * M_ + m] = s[h];
    }
}

// ---------------------------------------------------------------------------
// K4: flash attention, factored softmax (no exp/max in loop), FFMA2 gemms.
// Grid (N/64, H, 2), 256 threads.  Thread (ty=tid/16, tx=tid%16) owns
// S rows 4ty..4ty+3, cols 4tx..4tx+3 and O rows 4ty.., dims 4tx...
// 16B-chunk XOR swizzle, compile-time resolved via full unroll:
//   float index = row*68 + 4*((chunk) ^ ((row>>2)&7))
// ---------------------------------------------------------------------------
#define FP_ 68
#define SMIDX(row, chunk) ((row) * FP_ + 4 * ((chunk) ^ (((row) >> 2) & 7)))
#define SM_QT 0
#define SM_KT (SM_QT + 64 * FP_)
#define SM_VT (SM_KT + 64 * FP_)
#define SM_P  (SM_VT + 64 * FP_)
#define SM_F2 (SM_P  + 64 * FP_)
#define SM_U  (SM_F2 + 64)
#define SM_W  (SM_U  + 64)
#define SM_FLOATS (SM_W + 64)

__global__ void __launch_bounds__(256, 2) flash_kernel() {
    extern __shared__ float sm[];
    float* QT  = sm + SM_QT;
    float* KT  = sm + SM_KT;
    float* VT  = sm + SM_VT;
    float* P   = sm + SM_P;
    float* f2s = sm + SM_F2;
    float* us  = sm + SM_U;
    float* ws  = sm + SM_W;

    const int h  = blockIdx.y;
    const int i0 = blockIdx.x * 64;
    const int sp = blockIdx.z;            // KV split 0/1
    const int tid = threadIdx.x;
    const int ty = tid >> 4, tx = tid & 15;

    // Q tile
    for (int e = tid; e < 64 * 16; e += 256) {
        int r = e >> 4, c = e & 15;
        *(float4*)&QT[SMIDX(r, c)] =
            *(const float4*)&g_adjp[((size_t)h * N_ + i0 + r) * M_ + 4 * c];
    }
    // per-row constants: threshold t = -f1, ratio r = exp(-0.8 f1)
    float t_[4], r_[4];
    #pragma unroll
    for (int i = 0; i < 4; i++) {
        float f1v = g_f1[h * N_ + i0 + 4 * ty + i];
        t_[i] = -f1v;
        r_[i] = __expf(-0.8f * f1v);
    }

    float l_[4] = {0.f, 0.f, 0.f, 0.f};
    u64t o2[4][4] = {};                   // persistent packed O accumulators

    for (int jt = sp * 32; jt < sp * 32 + 32; jt++) {
        const int j0 = jt * 64;
        __syncthreads();   // prev-iter PV (reads P, VT) done before overwrite
        for (int e = tid; e < 64 * 16; e += 256) {
            int r = e >> 4, c = e & 15;
            *(float4*)&KT[SMIDX(r, c)] =
                *(const float4*)&g_adjp[((size_t)h * N_ + j0 + r) * M_ + 4 * c];
            *(float4*)&VT[SMIDX(r, c)] =
                *(const float4*)&g_WhT[((size_t)h * D_ + r) * N_ + j0 + 4 * c];
        }
        if (tid < 64) {
            f2s[tid] = g_f2[h * N_ + j0 + tid];
            us[tid]  = g_u [h * N_ + j0 + tid];
            ws[tid]  = g_w [h * N_ + j0 + tid];
        }
        __syncthreads();

        // ---- S = Q @ K^T (sign only), packed-k FFMA2, fully unrolled ----
        u64t s2[4][4] = {};
        #pragma unroll
        for (int kq = 0; kq < 16; kq++) {
            ulonglong2 A[4], B[4];
            #pragma unroll
            for (int i = 0; i < 4; i++)
                A[i] = *(const ulonglong2*)&QT[SMIDX(4 * ty + i, kq)];
            #pragma unroll
            for (int j = 0; j < 4; j++)
                B[j] = *(const ulonglong2*)&KT[SMIDX(4 * tx + j, kq)];
            #pragma unroll
            for (int i = 0; i < 4; i++)
                #pragma unroll
                for (int j = 0; j < 4; j++) {
                    FMA2(s2[i][j], A[i].x, B[j].x);
                    FMA2(s2[i][j], A[i].y, B[j].y);
                }
        }

        // ---- factored softmax weights (no exp, no reductions) ----
        float f2v[4], uv[4], wv[4];
        #pragma unroll
        for (int j = 0; j < 4; j++) {
            f2v[j] = f2s[4 * tx + j];
            uv[j]  = us[4 * tx + j];
            wv[j]  = ws[4 * tx + j];
        }
        float p[4][4];
        #pragma unroll
        for (int i = 0; i < 4; i++) {
            #pragma unroll
            for (int j = 0; j < 4; j++) {
                float sv = unpack_add(s2[i][j]);
                float pe = (f2v[j] > t_[i]) ? uv[j] : r_[i] * wv[j];
                pe = (sv > 0.f) ? pe : 0.f;
                p[i][j] = pe;
                l_[i] += pe;
            }
        }
        #pragma unroll
        for (int i = 0; i < 4; i++)
            *(float4*)&P[SMIDX(4 * ty + i, tx)] =
                make_float4(p[i][0], p[i][1], p[i][2], p[i][3]);
        __syncthreads();

        // ---- O += P @ V, packed-c FFMA2, fully unrolled ----
        #pragma unroll
        for (int cq = 0; cq < 16; cq++) {
            ulonglong2 A[4], B[4];
            #pragma unroll
            for (int i = 0; i < 4; i++)
                A[i] = *(const ulonglong2*)&P[SMIDX(4 * ty + i, cq)];
            #pragma unroll
            for (int j = 0; j < 4; j++)
                B[j] = *(const ulonglong2*)&VT[SMIDX(4 * tx + j, cq)];
            #pragma unroll
            for (int i = 0; i < 4; i++)
                #pragma unroll
                for (int j = 0; j < 4; j++) {
                    FMA2(o2[i][j], A[i].x, B[j].x);
                    FMA2(o2[i][j], A[i].y, B[j].y);
                }
        }
    }

    // reduce l across the 16 tx lanes of each row group
    #pragma unroll
    for (int i = 0; i < 4; i++) {
        #pragma unroll
        for (int off = 8; off; off >>= 1)
            l_[i] += __shfl_xor_sync(0xffffffffu, l_[i], off);
    }

    // partial epilogue: unnormalized o and l
    const int rowb = (sp * H_ + h) * N_ + i0;
    #pragma unroll
    for (int i = 0; i < 4; i++) {
        int rr = rowb + 4 * ty + i;
        if (tx == 0) g_pl[rr] = l_[i];
        *(float4*)&g_po[(size_t)rr * D_ + 4 * tx] =
            make_float4(unpack_add(o2[i][0]), unpack_add(o2[i][1]),
                        unpack_add(o2[i][2]), unpack_add(o2[i][3]));
    }
}

// ---------------------------------------------------------------------------
// K4b: merge the two KV splits, normalize, elu.  One thread per (h,n,d4).
// ---------------------------------------------------------------------------
__global__ void merge_kernel() {
    int idx = blockIdx.x * 256 + threadIdx.x;     // < H*N*16
    int d4 = (idx & 15) * 4;
    int hn = idx >> 4;
    float inv = 1.f / (g_pl[hn] + g_pl[HN_ + hn]);
    float4 o1 = *(const float4*)&g_po[(size_t)hn * D_ + d4];
    float4 o2 = *(const float4*)&g_po[(size_t)(HN_ + hn) * D_ + d4];
    float4 v;
    v.x = (o1.x + o2.x) * inv;
    v.y = (o1.y + o2.y) * inv;
    v.z = (o1.z + o2.z) * inv;
    v.w = (o1.w + o2.w) * inv;
    v.x = (v.x > 0.f) ? v.x : (__expf(v.x) - 1.f);
    v.y = (v.y > 0.f) ? v.y : (__expf(v.y) - 1.f);
    v.z = (v.z > 0.f) ? v.z : (__expf(v.z) - 1.f);
    v.w = (v.w > 0.f) ? v.w : (__expf(v.w) - 1.f);
    *(float4*)&g_head[(size_t)hn * D_ + d4] = v;
}

// ---------------------------------------------------------------------------
// K5: out = leaky( cat(heads) @ Wd + bd ).  Grid N/64, 256 threads.
// ---------------------------------------------------------------------------
__global__ void final_kernel(const float* __restrict__ Wd,
                             const float* __restrict__ bd,
                             float* __restrict__ out) {
    __shared__ float AT[64][68];
    __shared__ float Ws[64][64];
    const int n0 = blockIdx.x * 64;
    const int tid = threadIdx.x;
    const int ty = tid >> 4, tx = tid & 15;

    float acc[4][4] = {};

    for (int h = 0; h < H_; h++) {
        __syncthreads();
        for (int e = tid; e < 64 * 16; e += 256) {
            int r = e >> 4, k4 = (e & 15) * 4;
            float4 a = *(const float4*)&g_head[((size_t)h * N_ + n0 + r) * D_ + k4];
            AT[k4 + 0][r] = a.x;
            AT[k4 + 1][r] = a.y;
            AT[k4 + 2][r] = a.z;
            AT[k4 + 3][r] = a.w;
        }
        for (int e = tid; e < 64 * 16; e += 256) {
            int rr = e >> 4, c4 = (e & 15) * 4;
            *(float4*)&Ws[rr][c4] = *(const float4*)&Wd[(size_t)(h * 64 + rr) * D_ + c4];
        }
        __syncthreads();
        #pragma unroll 8
        for (int k = 0; k < 64; k++) {
            float4 a = *(float4*)&AT[k][4 * ty];
            float4 b = *(float4*)&Ws[k][4 * tx];
            acc[0][0] += a.x * b.x; acc[0][1] += a.x * b.y; acc[0][2] += a.x * b.z; acc[0][3] += a.x * b.w;
            acc[1][0] += a.y * b.x; acc[1][1] += a.y * b.y; acc[1][2] += a.y * b.z; acc[1][3] += a.y * b.w;
            acc[2][0] += a.z * b.x; acc[2][1] += a.z * b.y; acc[2][2] += a.z * b.z; acc[2][3] += a.z * b.w;
            acc[3][0] += a.w * b.x; acc[3][1] += a.w * b.y; acc[3][2] += a.w * b.z; acc[3][3] += a.w * b.w;
        }
    }
    #pragma unroll
    for (int j = 0; j < 4; j++) {
        float b = bd[4 * tx + j];
        #pragma unroll
        for (int i = 0; i < 4; i++) {
            float v = acc[i][j] + b;
            v = (v > 0.f) ? v : SLOPE_ * v;
            out[(size_t)(n0 + 4 * ty + i) * D_ + 4 * tx + j] = v;
        }
    }
}

// ---------------------------------------------------------------------------
extern "C" void kernel_launch(void* const* d_in, const int* in_sizes, int n_in,
                              void* d_out, int out_size) {
    const float* x    = (const float*)d_in[0];
    const float* mask = (const float*)d_in[1];
    const float* adj  = (const float*)d_in[2];
    const float* W    = (const float*)d_in[3];
    const float* a1   = (const float*)d_in[4];
    const float* a2   = (const float*)d_in[5];
    const float* aw   = (const float*)d_in[6];
    const float* Wd   = (const float*)d_in[7];
    const float* bd   = (const float*)d_in[8];
    float* out        = (float*)d_out;

    cudaFuncSetAttribute(flash_kernel,
                         cudaFuncAttributeMaxDynamicSharedMemorySize,
                         SM_FLOATS * (int)sizeof(float));

    wh_kernel<<<dim3(N_ / 64, H_), 256>>>(x, mask, W);
    f12_kernel<<<(H_ * N_) / 8, 256>>>(a1, a2);
    adjp_kernel<<<(N_ * M_) / 8, 256>>>(adj, aw);
    flash_kernel<<<dim3(N_ / 64, H_, 2), 256, SM_FLOATS * (int)sizeof(float)>>>();
    merge_kernel<<<(HN_ * 16) / 256, 256>>>();
    final_kernel<<<N_ / 64, 256>>>(Wd, bd, out);
}